// round 15
// baseline (speedup 1.0000x reference)
#include <cuda_runtime.h>
#include <cuda_fp16.h>
#include <cstdint>

#define BS_  2
#define SEQ  2048
#define EMB  1024
#define NH   16
#define HD   64
#define MROWS (BS_*SEQ)   // 4096

// scratch (device globals) — fp16 pipeline
__device__ __half g_q[BS_*SEQ*EMB];
__device__ __half g_k[BS_*SEQ*EMB];
__device__ __half g_vt[BS_*NH*HD*SEQ];   // V transposed: [b][h][d][s]
__device__ __half g_attn[BS_*SEQ*EMB];
__device__ __half g_aq[BS_*SEQ*EMB];
__device__ __half g_ak[BS_*SEQ*EMB];
__device__ __half g_av[BS_*SEQ*EMB];
__device__ __half g_wq[EMB*EMB];
__device__ __half g_wk[EMB*EMB];
__device__ __half g_wv[EMB*EMB];
__device__ __half g_wo[EMB*EMB];

__device__ __forceinline__ uint32_t h2(float lo, float hi) {
    uint32_t r; asm("cvt.rn.f16x2.f32 %0, %1, %2;" : "=r"(r) : "f"(hi), "f"(lo));
    return r;
}
__device__ __forceinline__ float tanh_fast(float x) {
    float r; asm("tanh.approx.f32 %0, %1;" : "=f"(r) : "f"(x)); return r;
}
__device__ __forceinline__ uint32_t smem_u32(const void* p) {
    uint32_t a;
    asm("{ .reg .u64 t; cvta.to.shared.u64 t, %1; cvt.u32.u64 %0, t; }"
        : "=r"(a) : "l"(p));
    return a;
}
__device__ __forceinline__ void ldsm4(uint32_t r[4], uint32_t a) {
    asm volatile("ldmatrix.sync.aligned.m8n8.x4.shared.b16 {%0,%1,%2,%3}, [%4];"
        : "=r"(r[0]), "=r"(r[1]), "=r"(r[2]), "=r"(r[3]) : "r"(a));
}
__device__ __forceinline__ void cpasync16(uint32_t saddr, const void* g) {
    asm volatile("cp.async.cg.shared.global [%0], [%1], 16;" :: "r"(saddr), "l"(g));
}
#define CP_COMMIT() asm volatile("cp.async.commit_group;" ::: "memory")
#define CP_WAIT1()  asm volatile("cp.async.wait_group 1;" ::: "memory")
#define CP_WAIT0()  asm volatile("cp.async.wait_group 0;" ::: "memory")

__device__ __forceinline__ void mma_f16(float c[4], const uint32_t a[4],
                                        const uint32_t b0, const uint32_t b1) {
    asm volatile(
        "mma.sync.aligned.m16n8k16.row.col.f32.f16.f16.f32 "
        "{%0,%1,%2,%3}, {%4,%5,%6,%7}, {%8,%9}, {%0,%1,%2,%3};"
        : "+f"(c[0]), "+f"(c[1]), "+f"(c[2]), "+f"(c[3])
        : "r"(a[0]), "r"(a[1]), "r"(a[2]), "r"(a[3]), "r"(b0), "r"(b1));
}
// exp(p) on [0,1]: degree-4 Chebyshev (max rel err ~1.8e-5), t = 2p-1
__device__ __forceinline__ float exp01(float p) {
    float t = fmaf(2.f, p, -1.f);
    float e = 0.00437510f;
    e = fmaf(e, t, 0.03501305f);
    e = fmaf(e, t, 0.20607264f);
    e = fmaf(e, t, 0.82412760f);
    e = fmaf(e, t, 1.64871112f);
    return e;
}

// ============================================================================
// fp32 -> fp16 conversion of 7 tensors in one launch
// ============================================================================
__global__ void half7_kernel(
    const float4* s0, uint2* d0, int n0,
    const float4* s1, uint2* d1, int n1,
    const float4* s2, uint2* d2, int n2,
    const float4* s3, uint2* d3, int n3,
    const float4* s4, uint2* d4, int n4,
    const float4* s5, uint2* d5, int n5,
    const float4* s6, uint2* d6, int n6)
{
    const float4* s; uint2* d; int n;
    switch (blockIdx.y) {
        case 0: s = s0; d = d0; n = n0; break;
        case 1: s = s1; d = d1; n = n1; break;
        case 2: s = s2; d = d2; n = n2; break;
        case 3: s = s3; d = d3; n = n3; break;
        case 4: s = s4; d = d4; n = n4; break;
        case 5: s = s5; d = d5; n = n5; break;
        default: s = s6; d = d6; n = n6; break;
    }
    for (int i = blockIdx.x * blockDim.x + threadIdx.x; i < n;
         i += gridDim.x * blockDim.x) {
        float4 v = __ldg(s + i);
        d[i] = make_uint2(h2(v.x, v.y), h2(v.z, v.w));
    }
}

// ============================================================================
// Projection GEMM (fp16 mma, f32 acc): C = A @ W^T + bias.  [R10 verbatim]
// CTA tile 128x128, warp 32x64, K-chunk 64 halves, 3-stage cp.async,
// ONE sync/chunk, ldmatrix, 2 CTAs/SM.
// mode per z: 0 = fp32 out, 1 = half out, 2 = half transposed Vt[b][h][d][s]
// ============================================================================
#define GST 144                 // smem row stride bytes (72 halves)
#define G_ATILE (128*GST)       // 18432 B
#define G_STAGE (2*G_ATILE)     // A+B per stage = 36864 B
#define G_SMEM  (3*G_STAGE)     // 110592 B
#define GBK 64                  // K-chunk (halves)
#define GNCHUNK (EMB/GBK)       // 16

__global__ void __launch_bounds__(256, 2) gemm_f16(
    const __half* __restrict__ A0, const __half* __restrict__ W0, const float* __restrict__ b0_, void* __restrict__ C0,
    const __half* __restrict__ A1, const __half* __restrict__ W1, const float* __restrict__ b1_, void* __restrict__ C1,
    const __half* __restrict__ A2, const __half* __restrict__ W2, const float* __restrict__ b2_, void* __restrict__ C2,
    int mode0, int mode1, int mode2)
{
    extern __shared__ char smc[];
    const uint32_t sb = smem_u32(smc);

    const __half* A    = blockIdx.z == 0 ? A0 : (blockIdx.z == 1 ? A1 : A2);
    const __half* W    = blockIdx.z == 0 ? W0 : (blockIdx.z == 1 ? W1 : W2);
    const float*  bias = blockIdx.z == 0 ? b0_ : (blockIdx.z == 1 ? b1_ : b2_);
    void*         C    = blockIdx.z == 0 ? C0 : (blockIdx.z == 1 ? C1 : C2);
    const int     mode = blockIdx.z == 0 ? mode0 : (blockIdx.z == 1 ? mode1 : mode2);

    const int tid  = threadIdx.x;
    const int lane = tid & 31;
    const int wid  = tid >> 5;
    const int wm   = wid >> 1;     // 0..3
    const int wn   = wid & 1;      // 0..1
    const int bm   = blockIdx.y * 128;
    const int bn   = blockIdx.x * 128;

    const __half* Ap = A + (long)bm * EMB;
    const __half* Wp = W + (long)bn * EMB;

    auto cpStage = [&](int c, int s) {
        int k0 = c * GBK;
        uint32_t sA = sb + (uint32_t)(s * G_STAGE);
        uint32_t sB = sA + G_ATILE;
        #pragma unroll
        for (int i = 0; i < 4; i++) {
            int id = tid + i * 256;
            int r = id >> 3, c8 = id & 7;
            uint32_t so = (uint32_t)(r * GST + c8 * 16);
            cpasync16(sA + so, Ap + (long)r * EMB + k0 + c8 * 8);
            cpasync16(sB + so, Wp + (long)r * EMB + k0 + c8 * 8);
        }
        CP_COMMIT();
    };

    float acc[2][8][4];
    #pragma unroll
    for (int mt = 0; mt < 2; mt++)
        #pragma unroll
        for (int nt = 0; nt < 8; nt++)
            #pragma unroll
            for (int j = 0; j < 4; j++) acc[mt][nt][j] = 0.f;

    cpStage(0, 0);
    cpStage(1, 1);

    const int a_row = lane & 15;
    const int a_kb  = (lane >> 4) * 16;
    const int b_row = (lane & 7) + 8 * (lane >> 4);
    const int b_kb  = ((lane >> 3) & 1) * 16;

    for (int c = 0; c < GNCHUNK; c++) {
        if (c + 2 < GNCHUNK) { CP_WAIT1(); } else { CP_WAIT0(); }
        __syncthreads();
        if (c + 2 < GNCHUNK) cpStage(c + 2, (c + 2) % 3);

        const uint32_t st = sb + (uint32_t)((c % 3) * G_STAGE);

        #pragma unroll
        for (int ks = 0; ks < 4; ks++) {
            uint32_t af[2][4], bf[8][2];
            #pragma unroll
            for (int mt = 0; mt < 2; mt++) {
                uint32_t addr = st + (uint32_t)((wm * 32 + mt * 16 + a_row) * GST + ks * 32 + a_kb);
                ldsm4(af[mt], addr);
            }
            #pragma unroll
            for (int g = 0; g < 4; g++) {
                uint32_t tmp[4];
                uint32_t addr = st + (uint32_t)(G_ATILE + (wn * 64 + g * 16 + b_row) * GST + ks * 32 + b_kb);
                ldsm4(tmp, addr);
                bf[2 * g][0] = tmp[0]; bf[2 * g][1] = tmp[1];
                bf[2 * g + 1][0] = tmp[2]; bf[2 * g + 1][1] = tmp[3];
            }
            #pragma unroll
            for (int mt = 0; mt < 2; mt++)
                #pragma unroll
                for (int nt = 0; nt < 8; nt++)
                    mma_f16(acc[mt][nt], af[mt], bf[nt][0], bf[nt][1]);
        }
        __syncthreads();
    }

    if (mode == 0) {
        float* Cf = (float*)C;
        #pragma unroll
        for (int mt = 0; mt < 2; mt++) {
            int r0 = bm + wm * 32 + mt * 16 + (lane >> 2);
            #pragma unroll
            for (int nt = 0; nt < 8; nt++) {
                int col = bn + wn * 64 + nt * 8 + (lane & 3) * 2;
                float2 bb = *(const float2*)(bias + col);
                float2 o0, o1;
                o0.x = acc[mt][nt][0] + bb.x; o0.y = acc[mt][nt][1] + bb.y;
                o1.x = acc[mt][nt][2] + bb.x; o1.y = acc[mt][nt][3] + bb.y;
                *(float2*)(Cf + (long)r0 * EMB + col) = o0;
                *(float2*)(Cf + (long)(r0 + 8) * EMB + col) = o1;
            }
        }
    } else if (mode == 1) {
        __half* Ch = (__half*)C;
        #pragma unroll
        for (int mt = 0; mt < 2; mt++) {
            int r0 = bm + wm * 32 + mt * 16 + (lane >> 2);
            #pragma unroll
            for (int nt = 0; nt < 8; nt++) {
                int col = bn + wn * 64 + nt * 8 + (lane & 3) * 2;
                float2 bb = *(const float2*)(bias + col);
                uint32_t w0 = h2(acc[mt][nt][0] + bb.x, acc[mt][nt][1] + bb.y);
                uint32_t w1 = h2(acc[mt][nt][2] + bb.x, acc[mt][nt][3] + bb.y);
                *(uint32_t*)(Ch + (long)r0 * EMB + col) = w0;
                *(uint32_t*)(Ch + (long)(r0 + 8) * EMB + col) = w1;
            }
        }
    } else {
        // transposed half: Vt[((b*NH+h)*HD + d)*SEQ + s]
        __half* Ch = (__half*)C;
        #pragma unroll
        for (int mt = 0; mt < 2; mt++) {
            int r0 = bm + wm * 32 + mt * 16 + (lane >> 2);
            int b_ = r0 >> 11, s = r0 & (SEQ - 1);
            #pragma unroll
            for (int nt = 0; nt < 8; nt++) {
                int col = bn + wn * 64 + nt * 8 + (lane & 3) * 2;
                int h = col >> 6, d = col & 63;
                float2 bb = *(const float2*)(bias + col);
                __half* base = Ch + ((long)((b_ * NH + h) * HD + d)) * SEQ + s;
                base[0]       = __float2half_rn(acc[mt][nt][0] + bb.x);
                base[SEQ]     = __float2half_rn(acc[mt][nt][1] + bb.y);
                base[8]       = __float2half_rn(acc[mt][nt][2] + bb.x);
                base[SEQ + 8] = __float2half_rn(acc[mt][nt][3] + bb.y);
            }
        }
    }
}

// ============================================================================
// Attention (fp16 mma, f32 acc): 128 queries x one (b,h) per CTA, 8 warps
// (each warp = identical 16-row x 64-key unit as R14), 64-key tiles,
// 2-stage cp.async, P repacked in REGISTERS, 2 CTAs/SM, 512 CTAs (1.73 waves).
// smem: stage s at s*18432 (K 9216 + V 9216), Q[128] at 36864. Total 55296 B.
// ============================================================================
#define A_KTILE 9216
#define A_STAGE 18432
#define A_QOFF  36864
#define A_BYTES 55296

__global__ void __launch_bounds__(256, 2) attn_f16(
    const __half* __restrict__ Q, const __half* __restrict__ K,
    const __half* __restrict__ Vt, const int* __restrict__ indicator,
    __half* __restrict__ O)
{
    extern __shared__ char smc[];
    const uint32_t sb = smem_u32(smc);
    const int tid  = threadIdx.x;
    const int lane = tid & 31;
    const int wid  = tid >> 5;             // 0..7 (query-row slice)
    const int b    = blockIdx.z;
    const int h    = blockIdx.y;
    const int q0   = blockIdx.x * 128;
    const int r    = lane >> 2;
    const int qq   = lane & 3;

    const float psign = __ldg(indicator) ? -0.5f : 0.5f;

    const int a_row = lane & 15;
    const int a_kb  = (lane >> 4) * 16;
    const int b_row = (lane & 7) + 8 * (lane >> 4);
    const int b_kb  = ((lane >> 3) & 1) * 16;

    // K/V tile: 64 rows x 8 chunks each = 1024 chunks over 256 threads
    auto cpKV = [&](int kt, int s) {
        uint32_t pk = sb + (uint32_t)(s * A_STAGE);
        uint32_t pv = pk + A_KTILE;
        #pragma unroll
        for (int i = 0; i < 2; i++) {
            int id = tid + i * 256;
            int rr = id >> 3, c8 = id & 7;
            uint32_t so = (uint32_t)(rr * GST + c8 * 16);
            cpasync16(pk + so, K + ((long)(b * SEQ + kt + rr)) * EMB + h * HD + c8 * 8);
            cpasync16(pv + so, Vt + ((long)((b * NH + h) * HD + rr)) * SEQ + kt + c8 * 8);
        }
        CP_COMMIT();
    };

    cpKV(0, 0);

    // stage Q tile [128 rows][64 halves] (raw 16B copies; already fp16)
    #pragma unroll
    for (int i = 0; i < 4; i++) {
        int id = tid + i * 256;
        int rr = id >> 3, c8 = id & 7;
        uint4 v = *(const uint4*)(Q + ((long)(b * SEQ + q0 + rr)) * EMB + h * HD + c8 * 8);
        *(uint4*)(smc + A_QOFF + rr * GST + c8 * 16) = v;
    }
    __syncthreads();

    uint32_t qf[4][4];
    #pragma unroll
    for (int ks = 0; ks < 4; ks++) {
        uint32_t addr = sb + (uint32_t)(A_QOFF + (wid * 16 + a_row) * GST + ks * 32 + a_kb);
        ldsm4(qf[ks], addr);
    }

    float oacc[8][4];
    #pragma unroll
    for (int nt = 0; nt < 8; nt++)
        #pragma unroll
        for (int j = 0; j < 4; j++) oacc[nt][j] = 0.f;
    float den0 = 0.f, den1 = 0.f;

    const int NT = SEQ / 64;
    for (int t = 0; t < NT; t++) {
        CP_WAIT0();
        __syncthreads();
        if (t + 1 < NT) cpKV((t + 1) * 64, (t + 1) & 1);

        const uint32_t stK = sb + (uint32_t)((t & 1) * A_STAGE);
        const uint32_t stV = stK + A_KTILE;

        // ---- S = Q @ K^T  (warp: 16 rows x 64 keys)
        float sacc[8][4];
        #pragma unroll
        for (int nt = 0; nt < 8; nt++)
            #pragma unroll
            for (int j = 0; j < 4; j++) sacc[nt][j] = 0.f;

        #pragma unroll
        for (int ks = 0; ks < 4; ks++) {
            #pragma unroll
            for (int g = 0; g < 4; g++) {
                uint32_t tmp[4];
                uint32_t addr = stK + (uint32_t)((g * 16 + b_row) * GST + ks * 32 + b_kb);
                ldsm4(tmp, addr);
                mma_f16(sacc[2 * g],     qf[ks], tmp[0], tmp[1]);
                mma_f16(sacc[2 * g + 1], qf[ks], tmp[2], tmp[3]);
            }
        }

        // ---- p = exp01(sigmoid(s/8)); pack fp16 A-frags in registers
        uint32_t pw[8][2];
        #pragma unroll
        for (int nt = 0; nt < 8; nt++) {
            float p0 = fmaf(psign, tanh_fast(sacc[nt][0] * 0.0625f), 0.5f);
            float p1 = fmaf(psign, tanh_fast(sacc[nt][1] * 0.0625f), 0.5f);
            float p2 = fmaf(psign, tanh_fast(sacc[nt][2] * 0.0625f), 0.5f);
            float p3 = fmaf(psign, tanh_fast(sacc[nt][3] * 0.0625f), 0.5f);
            p0 = exp01(p0); p1 = exp01(p1); p2 = exp01(p2); p3 = exp01(p3);
            den0 += p0 + p1;
            den1 += p2 + p3;
            pw[nt][0] = h2(p0, p1);
            pw[nt][1] = h2(p2, p3);
        }

        // ---- O += P @ V  (P from registers; V B-frags via ldmatrix)
        #pragma unroll
        for (int ks = 0; ks < 4; ks++) {
            uint32_t af[4] = { pw[2 * ks][0], pw[2 * ks][1],
                               pw[2 * ks + 1][0], pw[2 * ks + 1][1] };
            #pragma unroll
            for (int g = 0; g < 4; g++) {
                uint32_t tmp[4];
                uint32_t addr = stV + (uint32_t)((g * 16 + b_row) * GST + ks * 32 + b_kb);
                ldsm4(tmp, addr);
                mma_f16(oacc[2 * g],     af, tmp[0], tmp[1]);
                mma_f16(oacc[2 * g + 1], af, tmp[2], tmp[3]);
            }
        }
        __syncthreads();
    }

    den0 += __shfl_xor_sync(0xffffffffu, den0, 1);
    den0 += __shfl_xor_sync(0xffffffffu, den0, 2);
    den1 += __shfl_xor_sync(0xffffffffu, den1, 1);
    den1 += __shfl_xor_sync(0xffffffffu, den1, 2);
    float inv0 = 1.f / den0, inv1 = 1.f / den1;

    long row0 = (long)(b * SEQ + q0 + wid * 16 + r);
    #pragma unroll
    for (int nt = 0; nt < 8; nt++) {
        int col = h * HD + nt * 8 + qq * 2;
        uint32_t w0 = h2(oacc[nt][0] * inv0, oacc[nt][1] * inv0);
        uint32_t w1 = h2(oacc[nt][2] * inv1, oacc[nt][3] * inv1);
        *(uint32_t*)(O + row0 * EMB + col) = w0;
        *(uint32_t*)(O + (row0 + 8) * EMB + col) = w1;
    }
}

// ----------------------------------------------------------------------------
extern "C" void kernel_launch(void* const* d_in, const int* in_sizes, int n_in,
                              void* d_out, int out_size)
{
    const float* queries = (const float*)d_in[0];
    const float* keys    = (const float*)d_in[1];
    const float* values  = (const float*)d_in[2];
    const float* Wq = (const float*)d_in[3];
    const float* bq = (const float*)d_in[4];
    const float* Wk = (const float*)d_in[5];
    const float* bk = (const float*)d_in[6];
    const float* Wv = (const float*)d_in[7];
    const float* bv = (const float*)d_in[8];
    const float* Wo = (const float*)d_in[9];
    const float* bo = (const float*)d_in[10];
    const int* indicator = (const int*)d_in[11];

    __half *gq, *gk, *gvt, *ga, *gaq, *gak, *gav, *gwq, *gwk, *gwv, *gwo;
    cudaGetSymbolAddress((void**)&gq, g_q);
    cudaGetSymbolAddress((void**)&gk, g_k);
    cudaGetSymbolAddress((void**)&gvt, g_vt);
    cudaGetSymbolAddress((void**)&ga, g_attn);
    cudaGetSymbolAddress((void**)&gaq, g_aq);
    cudaGetSymbolAddress((void**)&gak, g_ak);
    cudaGetSymbolAddress((void**)&gav, g_av);
    cudaGetSymbolAddress((void**)&gwq, g_wq);
    cudaGetSymbolAddress((void**)&gwk, g_wk);
    cudaGetSymbolAddress((void**)&gwv, g_wv);
    cudaGetSymbolAddress((void**)&gwo, g_wo);

    static int attr_set = 0;
    if (!attr_set) {
        cudaFuncSetAttribute(gemm_f16,
                             cudaFuncAttributeMaxDynamicSharedMemorySize, G_SMEM);
        cudaFuncSetAttribute(attn_f16,
                             cudaFuncAttributeMaxDynamicSharedMemorySize, A_BYTES);
        attr_set = 1;
    }

    const int NACT4 = MROWS * EMB / 4;   // 1048576
    const int NW4   = EMB * EMB / 4;     // 262144
    dim3 h7_grid(512, 7);
    half7_kernel<<<h7_grid, 256>>>(
        (const float4*)queries, (uint2*)gaq, NACT4,
        (const float4*)keys,    (uint2*)gak, NACT4,
        (const float4*)values,  (uint2*)gav, NACT4,
        (const float4*)Wq, (uint2*)gwq, NW4,
        (const float4*)Wk, (uint2*)gwk, NW4,
        (const float4*)Wv, (uint2*)gwv, NW4,
        (const float4*)Wo, (uint2*)gwo, NW4);

    dim3 qkv_grid(EMB / 128, MROWS / 128, 3);   // (8, 32, 3) = 768 CTAs
    gemm_f16<<<qkv_grid, 256, G_SMEM>>>(
        gaq, gwq, bq, (void*)gq,
        gak, gwk, bk, (void*)gk,
        gav, gwv, bv, (void*)gvt,
        1, 1, 2);

    dim3 attn_grid(SEQ / 128, NH, BS_);         // (16, 16, 2) = 512 CTAs
    attn_f16<<<attn_grid, 256, A_BYTES>>>(gq, gk, gvt, indicator, ga);

    dim3 o_grid(EMB / 128, MROWS / 128, 1);     // 256 CTAs
    gemm_f16<<<o_grid, 256, G_SMEM>>>(
        ga, gwo, bo, d_out,
        ga, gwo, bo, d_out,
        ga, gwo, bo, d_out,
        0, 0, 0);
}

// round 16
// speedup vs baseline: 1.0744x; 1.0744x over previous
#include <cuda_runtime.h>
#include <cuda_fp16.h>
#include <cstdint>

#define BS_  2
#define SEQ  2048
#define EMB  1024
#define NH   16
#define HD   64
#define MROWS (BS_*SEQ)   // 4096

// scratch (device globals) — fp16 pipeline
__device__ __half g_q[BS_*SEQ*EMB];
__device__ __half g_k[BS_*SEQ*EMB];
__device__ __half g_vt[BS_*NH*HD*SEQ];   // V transposed: [b][h][d][s]
__device__ __half g_attn[BS_*SEQ*EMB];
__device__ __half g_aq[BS_*SEQ*EMB];
__device__ __half g_ak[BS_*SEQ*EMB];
__device__ __half g_av[BS_*SEQ*EMB];
__device__ __half g_wq[EMB*EMB];
__device__ __half g_wk[EMB*EMB];
__device__ __half g_wv[EMB*EMB];
__device__ __half g_wo[EMB*EMB];

__device__ __forceinline__ uint32_t h2(float lo, float hi) {
    uint32_t r; asm("cvt.rn.f16x2.f32 %0, %1, %2;" : "=r"(r) : "f"(hi), "f"(lo));
    return r;
}
__device__ __forceinline__ float tanh_fast(float x) {
    float r; asm("tanh.approx.f32 %0, %1;" : "=f"(r) : "f"(x)); return r;
}
__device__ __forceinline__ uint32_t smem_u32(const void* p) {
    uint32_t a;
    asm("{ .reg .u64 t; cvta.to.shared.u64 t, %1; cvt.u32.u64 %0, t; }"
        : "=r"(a) : "l"(p));
    return a;
}
__device__ __forceinline__ void ldsm4(uint32_t r[4], uint32_t a) {
    asm volatile("ldmatrix.sync.aligned.m8n8.x4.shared.b16 {%0,%1,%2,%3}, [%4];"
        : "=r"(r[0]), "=r"(r[1]), "=r"(r[2]), "=r"(r[3]) : "r"(a));
}
__device__ __forceinline__ void cpasync16(uint32_t saddr, const void* g) {
    asm volatile("cp.async.cg.shared.global [%0], [%1], 16;" :: "r"(saddr), "l"(g));
}
#define CP_COMMIT() asm volatile("cp.async.commit_group;" ::: "memory")
#define CP_WAIT1()  asm volatile("cp.async.wait_group 1;" ::: "memory")
#define CP_WAIT0()  asm volatile("cp.async.wait_group 0;" ::: "memory")

__device__ __forceinline__ void mma_f16(float c[4], const uint32_t a[4],
                                        const uint32_t b0, const uint32_t b1) {
    asm volatile(
        "mma.sync.aligned.m16n8k16.row.col.f32.f16.f16.f32 "
        "{%0,%1,%2,%3}, {%4,%5,%6,%7}, {%8,%9}, {%0,%1,%2,%3};"
        : "+f"(c[0]), "+f"(c[1]), "+f"(c[2]), "+f"(c[3])
        : "r"(a[0]), "r"(a[1]), "r"(a[2]), "r"(a[3]), "r"(b0), "r"(b1));
}
// exp(p) on [0,1]: degree-4 Chebyshev (max rel err ~1.8e-5), t = 2p-1
__device__ __forceinline__ float exp01(float p) {
    float t = fmaf(2.f, p, -1.f);
    float e = 0.00437510f;
    e = fmaf(e, t, 0.03501305f);
    e = fmaf(e, t, 0.20607264f);
    e = fmaf(e, t, 0.82412760f);
    e = fmaf(e, t, 1.64871112f);
    return e;
}

// ============================================================================
// fp32 -> fp16 conversion, FLAT balanced grid-stride over all 7 tensors
// layout: [0, 3*NACT4) activations q/k/v ; [3*NACT4, +4*NW4) weights q/k/v/o
// ============================================================================
#define NACT4 (MROWS*EMB/4)       // 1048576 float4 per activation
#define NW4   (EMB*EMB/4)         // 262144 float4 per weight
#define NTOT4 (3*NACT4 + 4*NW4)   // 4194304

__global__ void half7_flat(
    const float4* __restrict__ sq, const float4* __restrict__ sk, const float4* __restrict__ sv,
    const float4* __restrict__ w0, const float4* __restrict__ w1,
    const float4* __restrict__ w2, const float4* __restrict__ w3,
    uint2* __restrict__ dq, uint2* __restrict__ dk, uint2* __restrict__ dv,
    uint2* __restrict__ e0, uint2* __restrict__ e1,
    uint2* __restrict__ e2, uint2* __restrict__ e3)
{
    for (int i = blockIdx.x * blockDim.x + threadIdx.x; i < NTOT4;
         i += gridDim.x * blockDim.x) {
        const float4* s; uint2* d; int off;
        if (i < 3 * NACT4) {
            int t = i / NACT4; off = i - t * NACT4;
            s = t == 0 ? sq : (t == 1 ? sk : sv);
            d = t == 0 ? dq : (t == 1 ? dk : dv);
        } else {
            int j = i - 3 * NACT4;
            int t = j / NW4; off = j - t * NW4;
            s = t == 0 ? w0 : (t == 1 ? w1 : (t == 2 ? w2 : w3));
            d = t == 0 ? e0 : (t == 1 ? e1 : (t == 2 ? e2 : e3));
        }
        float4 v = __ldg(s + off);
        d[off] = make_uint2(h2(v.x, v.y), h2(v.z, v.w));
    }
}

// ============================================================================
// Projection GEMM (fp16 mma, f32 acc): C = A @ W^T + bias.
// CTA tile 128x128, warp 32x64, K-chunk 64 halves, 3-stage cp.async,
// ONE sync/chunk (trailing barrier removed — top barrier orders stage reuse),
// ldmatrix, 2 CTAs/SM.
// mode per z: 0 = fp32 out, 1 = half out, 2 = half transposed Vt[b][h][d][s]
// ============================================================================
#define GST 144                 // smem row stride bytes (72 halves)
#define G_ATILE (128*GST)       // 18432 B
#define G_STAGE (2*G_ATILE)     // A+B per stage = 36864 B
#define G_SMEM  (3*G_STAGE)     // 110592 B
#define GBK 64                  // K-chunk (halves)
#define GNCHUNK (EMB/GBK)       // 16

__global__ void __launch_bounds__(256, 2) gemm_f16(
    const __half* __restrict__ A0, const __half* __restrict__ W0, const float* __restrict__ b0_, void* __restrict__ C0,
    const __half* __restrict__ A1, const __half* __restrict__ W1, const float* __restrict__ b1_, void* __restrict__ C1,
    const __half* __restrict__ A2, const __half* __restrict__ W2, const float* __restrict__ b2_, void* __restrict__ C2,
    int mode0, int mode1, int mode2)
{
    extern __shared__ char smc[];
    const uint32_t sb = smem_u32(smc);

    const __half* A    = blockIdx.z == 0 ? A0 : (blockIdx.z == 1 ? A1 : A2);
    const __half* W    = blockIdx.z == 0 ? W0 : (blockIdx.z == 1 ? W1 : W2);
    const float*  bias = blockIdx.z == 0 ? b0_ : (blockIdx.z == 1 ? b1_ : b2_);
    void*         C    = blockIdx.z == 0 ? C0 : (blockIdx.z == 1 ? C1 : C2);
    const int     mode = blockIdx.z == 0 ? mode0 : (blockIdx.z == 1 ? mode1 : mode2);

    const int tid  = threadIdx.x;
    const int lane = tid & 31;
    const int wid  = tid >> 5;
    const int wm   = wid >> 1;     // 0..3
    const int wn   = wid & 1;      // 0..1
    const int bm   = blockIdx.y * 128;
    const int bn   = blockIdx.x * 128;

    const __half* Ap = A + (long)bm * EMB;
    const __half* Wp = W + (long)bn * EMB;

    auto cpStage = [&](int c, int s) {
        int k0 = c * GBK;
        uint32_t sA = sb + (uint32_t)(s * G_STAGE);
        uint32_t sB = sA + G_ATILE;
        #pragma unroll
        for (int i = 0; i < 4; i++) {
            int id = tid + i * 256;
            int r = id >> 3, c8 = id & 7;
            uint32_t so = (uint32_t)(r * GST + c8 * 16);
            cpasync16(sA + so, Ap + (long)r * EMB + k0 + c8 * 8);
            cpasync16(sB + so, Wp + (long)r * EMB + k0 + c8 * 8);
        }
        CP_COMMIT();
    };

    float acc[2][8][4];
    #pragma unroll
    for (int mt = 0; mt < 2; mt++)
        #pragma unroll
        for (int nt = 0; nt < 8; nt++)
            #pragma unroll
            for (int j = 0; j < 4; j++) acc[mt][nt][j] = 0.f;

    cpStage(0, 0);
    cpStage(1, 1);

    const int a_row = lane & 15;
    const int a_kb  = (lane >> 4) * 16;
    const int b_row = (lane & 7) + 8 * (lane >> 4);
    const int b_kb  = ((lane >> 3) & 1) * 16;

    for (int c = 0; c < GNCHUNK; c++) {
        if (c + 2 < GNCHUNK) { CP_WAIT1(); } else { CP_WAIT0(); }
        __syncthreads();   // orders: cp(c) visible; all reads of stage (c+2)%3 done
        if (c + 2 < GNCHUNK) cpStage(c + 2, (c + 2) % 3);

        const uint32_t st = sb + (uint32_t)((c % 3) * G_STAGE);

        #pragma unroll
        for (int ks = 0; ks < 4; ks++) {
            uint32_t af[2][4], bf[8][2];
            #pragma unroll
            for (int mt = 0; mt < 2; mt++) {
                uint32_t addr = st + (uint32_t)((wm * 32 + mt * 16 + a_row) * GST + ks * 32 + a_kb);
                ldsm4(af[mt], addr);
            }
            #pragma unroll
            for (int g = 0; g < 4; g++) {
                uint32_t tmp[4];
                uint32_t addr = st + (uint32_t)(G_ATILE + (wn * 64 + g * 16 + b_row) * GST + ks * 32 + b_kb);
                ldsm4(tmp, addr);
                bf[2 * g][0] = tmp[0]; bf[2 * g][1] = tmp[1];
                bf[2 * g + 1][0] = tmp[2]; bf[2 * g + 1][1] = tmp[3];
            }
            #pragma unroll
            for (int mt = 0; mt < 2; mt++)
                #pragma unroll
                for (int nt = 0; nt < 8; nt++)
                    mma_f16(acc[mt][nt], af[mt], bf[nt][0], bf[nt][1]);
        }
        // trailing __syncthreads removed: next iteration's top barrier suffices
    }

    if (mode == 0) {
        float* Cf = (float*)C;
        #pragma unroll
        for (int mt = 0; mt < 2; mt++) {
            int r0 = bm + wm * 32 + mt * 16 + (lane >> 2);
            #pragma unroll
            for (int nt = 0; nt < 8; nt++) {
                int col = bn + wn * 64 + nt * 8 + (lane & 3) * 2;
                float2 bb = *(const float2*)(bias + col);
                float2 o0, o1;
                o0.x = acc[mt][nt][0] + bb.x; o0.y = acc[mt][nt][1] + bb.y;
                o1.x = acc[mt][nt][2] + bb.x; o1.y = acc[mt][nt][3] + bb.y;
                *(float2*)(Cf + (long)r0 * EMB + col) = o0;
                *(float2*)(Cf + (long)(r0 + 8) * EMB + col) = o1;
            }
        }
    } else if (mode == 1) {
        __half* Ch = (__half*)C;
        #pragma unroll
        for (int mt = 0; mt < 2; mt++) {
            int r0 = bm + wm * 32 + mt * 16 + (lane >> 2);
            #pragma unroll
            for (int nt = 0; nt < 8; nt++) {
                int col = bn + wn * 64 + nt * 8 + (lane & 3) * 2;
                float2 bb = *(const float2*)(bias + col);
                uint32_t w0 = h2(acc[mt][nt][0] + bb.x, acc[mt][nt][1] + bb.y);
                uint32_t w1 = h2(acc[mt][nt][2] + bb.x, acc[mt][nt][3] + bb.y);
                *(uint32_t*)(Ch + (long)r0 * EMB + col) = w0;
                *(uint32_t*)(Ch + (long)(r0 + 8) * EMB + col) = w1;
            }
        }
    } else {
        // transposed half: Vt[((b*NH+h)*HD + d)*SEQ + s]
        __half* Ch = (__half*)C;
        #pragma unroll
        for (int mt = 0; mt < 2; mt++) {
            int r0 = bm + wm * 32 + mt * 16 + (lane >> 2);
            int b_ = r0 >> 11, s = r0 & (SEQ - 1);
            #pragma unroll
            for (int nt = 0; nt < 8; nt++) {
                int col = bn + wn * 64 + nt * 8 + (lane & 3) * 2;
                int h = col >> 6, d = col & 63;
                float2 bb = *(const float2*)(bias + col);
                __half* base = Ch + ((long)((b_ * NH + h) * HD + d)) * SEQ + s;
                base[0]       = __float2half_rn(acc[mt][nt][0] + bb.x);
                base[SEQ]     = __float2half_rn(acc[mt][nt][1] + bb.y);
                base[8]       = __float2half_rn(acc[mt][nt][2] + bb.x);
                base[SEQ + 8] = __float2half_rn(acc[mt][nt][3] + bb.y);
            }
        }
    }
}

// ============================================================================
// Attention (fp16 mma, f32 acc)  [R14 structure, trailing barrier removed]:
// w = sigmoid(qk/8) in [0,1] -> exp in [1,e], single pass, no running max.
// CTA: 64 queries x one (b,h); 4 warps; 64-key tiles; 2-stage cp.async;
// P repacked in REGISTERS; 3 CTAs/SM (12 warps).
// smem: stage s at s*18432 (K 9216 + V 9216), Q at 36864. Total 46080 B.
// ============================================================================
#define A_KTILE 9216
#define A_STAGE 18432
#define A_QOFF  36864
#define A_BYTES 46080

__global__ void __launch_bounds__(128, 3) attn_f16(
    const __half* __restrict__ Q, const __half* __restrict__ K,
    const __half* __restrict__ Vt, const int* __restrict__ indicator,
    __half* __restrict__ O)
{
    extern __shared__ char smc[];
    const uint32_t sb = smem_u32(smc);
    const int tid  = threadIdx.x;
    const int lane = tid & 31;
    const int wid  = tid >> 5;             // 0..3
    const int b    = blockIdx.z;
    const int h    = blockIdx.y;
    const int q0   = blockIdx.x * 64;
    const int r    = lane >> 2;
    const int qq   = lane & 3;

    const float psign = __ldg(indicator) ? -0.5f : 0.5f;

    const int a_row = lane & 15;
    const int a_kb  = (lane >> 4) * 16;
    const int b_row = (lane & 7) + 8 * (lane >> 4);
    const int b_kb  = ((lane >> 3) & 1) * 16;

    auto cpKV = [&](int kt, int s) {
        uint32_t pk = sb + (uint32_t)(s * A_STAGE);
        uint32_t pv = pk + A_KTILE;
        #pragma unroll
        for (int i = 0; i < 4; i++) {
            int id = tid + i * 128;
            int rr = id >> 3, c8 = id & 7;
            uint32_t so = (uint32_t)(rr * GST + c8 * 16);
            cpasync16(pk + so, K + ((long)(b * SEQ + kt + rr)) * EMB + h * HD + c8 * 8);
            cpasync16(pv + so, Vt + ((long)((b * NH + h) * HD + rr)) * SEQ + kt + c8 * 8);
        }
        CP_COMMIT();
    };

    cpKV(0, 0);

    // stage Q tile [64 rows][64 halves] (raw 16B copies; already fp16)
    #pragma unroll
    for (int i = 0; i < 4; i++) {
        int id = tid + i * 128;
        int rr = id >> 3, c8 = id & 7;
        uint4 v = *(const uint4*)(Q + ((long)(b * SEQ + q0 + rr)) * EMB + h * HD + c8 * 8);
        *(uint4*)(smc + A_QOFF + rr * GST + c8 * 16) = v;
    }
    __syncthreads();

    uint32_t qf[4][4];
    #pragma unroll
    for (int ks = 0; ks < 4; ks++) {
        uint32_t addr = sb + (uint32_t)(A_QOFF + (wid * 16 + a_row) * GST + ks * 32 + a_kb);
        ldsm4(qf[ks], addr);
    }

    float oacc[8][4];
    #pragma unroll
    for (int nt = 0; nt < 8; nt++)
        #pragma unroll
        for (int j = 0; j < 4; j++) oacc[nt][j] = 0.f;
    float den0 = 0.f, den1 = 0.f;

    const int NT = SEQ / 64;
    for (int t = 0; t < NT; t++) {
        CP_WAIT0();
        __syncthreads();   // orders cp(t) visible + all reads of stage t&1 done
        if (t + 1 < NT) cpKV((t + 1) * 64, (t + 1) & 1);

        const uint32_t stK = sb + (uint32_t)((t & 1) * A_STAGE);
        const uint32_t stV = stK + A_KTILE;

        // ---- S = Q @ K^T  (warp: 16 rows x 64 keys)
        float sacc[8][4];
        #pragma unroll
        for (int nt = 0; nt < 8; nt++)
            #pragma unroll
            for (int j = 0; j < 4; j++) sacc[nt][j] = 0.f;

        #pragma unroll
        for (int ks = 0; ks < 4; ks++) {
            #pragma unroll
            for (int g = 0; g < 4; g++) {
                uint32_t tmp[4];
                uint32_t addr = stK + (uint32_t)((g * 16 + b_row) * GST + ks * 32 + b_kb);
                ldsm4(tmp, addr);
                mma_f16(sacc[2 * g],     qf[ks], tmp[0], tmp[1]);
                mma_f16(sacc[2 * g + 1], qf[ks], tmp[2], tmp[3]);
            }
        }

        // ---- p = exp01(sigmoid(s/8)); pack fp16 A-frags in registers
        uint32_t pw[8][2];
        #pragma unroll
        for (int nt = 0; nt < 8; nt++) {
            float p0 = fmaf(psign, tanh_fast(sacc[nt][0] * 0.0625f), 0.5f);
            float p1 = fmaf(psign, tanh_fast(sacc[nt][1] * 0.0625f), 0.5f);
            float p2 = fmaf(psign, tanh_fast(sacc[nt][2] * 0.0625f), 0.5f);
            float p3 = fmaf(psign, tanh_fast(sacc[nt][3] * 0.0625f), 0.5f);
            p0 = exp01(p0); p1 = exp01(p1); p2 = exp01(p2); p3 = exp01(p3);
            den0 += p0 + p1;
            den1 += p2 + p3;
            pw[nt][0] = h2(p0, p1);
            pw[nt][1] = h2(p2, p3);
        }

        // ---- O += P @ V  (P from registers; V B-frags via ldmatrix)
        #pragma unroll
        for (int ks = 0; ks < 4; ks++) {
            uint32_t af[4] = { pw[2 * ks][0], pw[2 * ks][1],
                               pw[2 * ks + 1][0], pw[2 * ks + 1][1] };
            #pragma unroll
            for (int g = 0; g < 4; g++) {
                uint32_t tmp[4];
                uint32_t addr = stV + (uint32_t)((g * 16 + b_row) * GST + ks * 32 + b_kb);
                ldsm4(tmp, addr);
                mma_f16(oacc[2 * g],     af, tmp[0], tmp[1]);
                mma_f16(oacc[2 * g + 1], af, tmp[2], tmp[3]);
            }
        }
        // trailing __syncthreads removed: next iteration's top barrier suffices
    }

    den0 += __shfl_xor_sync(0xffffffffu, den0, 1);
    den0 += __shfl_xor_sync(0xffffffffu, den0, 2);
    den1 += __shfl_xor_sync(0xffffffffu, den1, 1);
    den1 += __shfl_xor_sync(0xffffffffu, den1, 2);
    float inv0 = 1.f / den0, inv1 = 1.f / den1;

    long row0 = (long)(b * SEQ + q0 + wid * 16 + r);
    #pragma unroll
    for (int nt = 0; nt < 8; nt++) {
        int col = h * HD + nt * 8 + qq * 2;
        uint32_t w0 = h2(oacc[nt][0] * inv0, oacc[nt][1] * inv0);
        uint32_t w1 = h2(oacc[nt][2] * inv1, oacc[nt][3] * inv1);
        *(uint32_t*)(O + row0 * EMB + col) = w0;
        *(uint32_t*)(O + (row0 + 8) * EMB + col) = w1;
    }
}

// ----------------------------------------------------------------------------
extern "C" void kernel_launch(void* const* d_in, const int* in_sizes, int n_in,
                              void* d_out, int out_size)
{
    const float* queries = (const float*)d_in[0];
    const float* keys    = (const float*)d_in[1];
    const float* values  = (const float*)d_in[2];
    const float* Wq = (const float*)d_in[3];
    const float* bq = (const float*)d_in[4];
    const float* Wk = (const float*)d_in[5];
    const float* bk = (const float*)d_in[6];
    const float* Wv = (const float*)d_in[7];
    const float* bv = (const float*)d_in[8];
    const float* Wo = (const float*)d_in[9];
    const float* bo = (const float*)d_in[10];
    const int* indicator = (const int*)d_in[11];

    __half *gq, *gk, *gvt, *ga, *gaq, *gak, *gav, *gwq, *gwk, *gwv, *gwo;
    cudaGetSymbolAddress((void**)&gq, g_q);
    cudaGetSymbolAddress((void**)&gk, g_k);
    cudaGetSymbolAddress((void**)&gvt, g_vt);
    cudaGetSymbolAddress((void**)&ga, g_attn);
    cudaGetSymbolAddress((void**)&gaq, g_aq);
    cudaGetSymbolAddress((void**)&gak, g_ak);
    cudaGetSymbolAddress((void**)&gav, g_av);
    cudaGetSymbolAddress((void**)&gwq, g_wq);
    cudaGetSymbolAddress((void**)&gwk, g_wk);
    cudaGetSymbolAddress((void**)&gwv, g_wv);
    cudaGetSymbolAddress((void**)&gwo, g_wo);

    static int attr_set = 0;
    if (!attr_set) {
        cudaFuncSetAttribute(gemm_f16,
                             cudaFuncAttributeMaxDynamicSharedMemorySize, G_SMEM);
        cudaFuncSetAttribute(attn_f16,
                             cudaFuncAttributeMaxDynamicSharedMemorySize, A_BYTES);
        attr_set = 1;
    }

    half7_flat<<<1184, 256>>>(
        (const float4*)queries, (const float4*)keys, (const float4*)values,
        (const float4*)Wq, (const float4*)Wk, (const float4*)Wv, (const float4*)Wo,
        (uint2*)gaq, (uint2*)gak, (uint2*)gav,
        (uint2*)gwq, (uint2*)gwk, (uint2*)gwv, (uint2*)gwo);

    dim3 qkv_grid(EMB / 128, MROWS / 128, 3);   // (8, 32, 3) = 768 CTAs
    gemm_f16<<<qkv_grid, 256, G_SMEM>>>(
        gaq, gwq, bq, (void*)gq,
        gak, gwk, bk, (void*)gk,
        gav, gwv, bv, (void*)gvt,
        1, 1, 2);

    dim3 attn_grid(SEQ / 64, NH, BS_);          // 1024 CTAs
    attn_f16<<<attn_grid, 128, A_BYTES>>>(gq, gk, gvt, indicator, ga);

    dim3 o_grid(EMB / 128, MROWS / 128, 1);     // 256 CTAs
    gemm_f16<<<o_grid, 256, G_SMEM>>>(
        ga, gwo, bo, d_out,
        ga, gwo, bo, d_out,
        ga, gwo, bo, d_out,
        0, 0, 0);
}